// round 1
// baseline (speedup 1.0000x reference)
#include <cuda_runtime.h>
#include <cuda_bf16.h>

// ---------------------------------------------------------------------------
// Net_7335804141892: 3x GCSConv (out = relu(A@(xW1) + xW2 + b)) -> global avg
// pool per graph -> dense(32->2) -> softmax.
// N=50000 nodes, E=800000 edges, G=256 graphs, channels 30->128->64->32.
// ---------------------------------------------------------------------------

#define NN 50000
#define GG 256

// Scratch (device globals; no allocation allowed).
__device__ float g_h [NN * 128];   // h = x @ W1 (per layer, reused)
__device__ float g_a1[NN * 128];   // layer1 pre-relu output
__device__ float g_a2[NN * 64];    // layer2 pre-relu output
__device__ float g_a3[NN * 32];    // layer3 pre-relu output
__device__ float g_pool[GG * 32];  // per-graph feature sums
__device__ float g_cnt [GG];       // per-graph node counts

// ---------------------------------------------------------------------------
// Dual GEMM: H[i,:] = act(X[i,:]) @ W1 ;  A[i,:] = act(X[i,:]) @ W2 + b
// act = relu for layers 2,3 (inputs are stored pre-relu).
// Each thread: 4 rows x 4 cols x 2 matrices -> 1B shared traffic per FMA.
// ---------------------------------------------------------------------------
template <int FIN, int FOUT, bool RELU_IN>
__global__ void __launch_bounds__(256) gemm_dual(
    const float* __restrict__ X,
    const float* __restrict__ W1,
    const float* __restrict__ W2,
    const float* __restrict__ Bv,
    float* __restrict__ H,
    float* __restrict__ A,
    int n)
{
    constexpr int TPR = FOUT / 4;      // threads covering one row (4 cols each)
    constexpr int RG  = 256 / TPR;     // row-groups per block
    constexpr int R   = 4;             // rows per thread

    extern __shared__ float sm[];
    float* sW1 = sm;
    float* sW2 = sm + FIN * FOUT;
    float* sB  = sm + 2 * FIN * FOUT;

    for (int i = threadIdx.x; i < FIN * FOUT; i += 256) {
        sW1[i] = W1[i];
        sW2[i] = W2[i];
    }
    for (int i = threadIdx.x; i < FOUT; i += 256) sB[i] = Bv[i];
    __syncthreads();

    const int c4   = (threadIdx.x % TPR) * 4;
    const int rg   = threadIdx.x / TPR;
    const int row0 = (blockIdx.x * RG + rg) * R;
    if (row0 >= n) return;

    float acc1[R][4];
    float acc2[R][4];
#pragma unroll
    for (int r = 0; r < R; r++)
#pragma unroll
        for (int j = 0; j < 4; j++) { acc1[r][j] = 0.f; acc2[r][j] = 0.f; }

    const bool full = (row0 + R <= n);

    if (full) {
#pragma unroll 4
        for (int k = 0; k < FIN; k++) {
            const float4 w1v = *(const float4*)&sW1[k * FOUT + c4];
            const float4 w2v = *(const float4*)&sW2[k * FOUT + c4];
#pragma unroll
            for (int r = 0; r < R; r++) {
                float xv = __ldg(&X[(size_t)(row0 + r) * FIN + k]);
                if (RELU_IN) xv = fmaxf(xv, 0.f);
                acc1[r][0] = fmaf(xv, w1v.x, acc1[r][0]);
                acc1[r][1] = fmaf(xv, w1v.y, acc1[r][1]);
                acc1[r][2] = fmaf(xv, w1v.z, acc1[r][2]);
                acc1[r][3] = fmaf(xv, w1v.w, acc1[r][3]);
                acc2[r][0] = fmaf(xv, w2v.x, acc2[r][0]);
                acc2[r][1] = fmaf(xv, w2v.y, acc2[r][1]);
                acc2[r][2] = fmaf(xv, w2v.z, acc2[r][2]);
                acc2[r][3] = fmaf(xv, w2v.w, acc2[r][3]);
            }
        }
    } else {
        for (int k = 0; k < FIN; k++) {
            const float4 w1v = *(const float4*)&sW1[k * FOUT + c4];
            const float4 w2v = *(const float4*)&sW2[k * FOUT + c4];
#pragma unroll
            for (int r = 0; r < R; r++) {
                int row = row0 + r;
                float xv = (row < n) ? __ldg(&X[(size_t)row * FIN + k]) : 0.f;
                if (RELU_IN) xv = fmaxf(xv, 0.f);
                acc1[r][0] = fmaf(xv, w1v.x, acc1[r][0]);
                acc1[r][1] = fmaf(xv, w1v.y, acc1[r][1]);
                acc1[r][2] = fmaf(xv, w1v.z, acc1[r][2]);
                acc1[r][3] = fmaf(xv, w1v.w, acc1[r][3]);
                acc2[r][0] = fmaf(xv, w2v.x, acc2[r][0]);
                acc2[r][1] = fmaf(xv, w2v.y, acc2[r][1]);
                acc2[r][2] = fmaf(xv, w2v.z, acc2[r][2]);
                acc2[r][3] = fmaf(xv, w2v.w, acc2[r][3]);
            }
        }
    }

    const float4 bb = *(const float4*)&sB[c4];
#pragma unroll
    for (int r = 0; r < R; r++) {
        int row = row0 + r;
        if (row < n) {
            float4 o1 = make_float4(acc1[r][0], acc1[r][1], acc1[r][2], acc1[r][3]);
            float4 o2 = make_float4(acc2[r][0] + bb.x, acc2[r][1] + bb.y,
                                    acc2[r][2] + bb.z, acc2[r][3] + bb.w);
            *(float4*)&H[(size_t)row * FOUT + c4] = o1;
            *(float4*)&A[(size_t)row * FOUT + c4] = o2;
        }
    }
}

// ---------------------------------------------------------------------------
// Edge scatter: A[er[e], :] += ew[e] * H[ec[e], :]   (vector f32 red to L2)
// One thread per (edge, 4-col chunk).
// ---------------------------------------------------------------------------
template <int FOUT>
__global__ void __launch_bounds__(256) scatter_edges(
    const float* __restrict__ H,
    const int*   __restrict__ er,
    const int*   __restrict__ ec,
    const float* __restrict__ ew,
    float* __restrict__ A,
    int E)
{
    constexpr int CPE = FOUT / 4;          // chunks per edge (power of 2)
    int t = blockIdx.x * blockDim.x + threadIdx.x;
    if (t >= E * CPE) return;
    int e = t / CPE;
    int c = (t % CPE) * 4;

    int   r   = __ldg(&er[e]);
    int   src = __ldg(&ec[e]);
    float w   = __ldg(&ew[e]);

    const float4 h = *(const float4*)&H[(size_t)src * FOUT + c];
    float4 v = make_float4(w * h.x, w * h.y, w * h.z, w * h.w);
    float* dst = &A[(size_t)r * FOUT + c];
    asm volatile("red.global.add.v4.f32 [%0], {%1,%2,%3,%4};"
                 :: "l"(dst), "f"(v.x), "f"(v.y), "f"(v.z), "f"(v.w)
                 : "memory");
}

// ---------------------------------------------------------------------------
// Pool helpers
// ---------------------------------------------------------------------------
__global__ void zero_pool_kernel()
{
    int t = blockIdx.x * blockDim.x + threadIdx.x;
    if (t < GG * 32) g_pool[t] = 0.f;
    if (t < GG)      g_cnt[t]  = 0.f;
}

__global__ void pool_kernel(const float* __restrict__ A,
                            const int* __restrict__ seg, int n)
{
    int t = blockIdx.x * blockDim.x + threadIdx.x;
    if (t >= n * 8) return;
    int node = t >> 3;
    int c    = (t & 7) * 4;
    int g    = __ldg(&seg[node]);
    float4 v = *(const float4*)&A[(size_t)node * 32 + c];
    v.x = fmaxf(v.x, 0.f); v.y = fmaxf(v.y, 0.f);
    v.z = fmaxf(v.z, 0.f); v.w = fmaxf(v.w, 0.f);
    float* dst = &g_pool[g * 32 + c];
    asm volatile("red.global.add.v4.f32 [%0], {%1,%2,%3,%4};"
                 :: "l"(dst), "f"(v.x), "f"(v.y), "f"(v.z), "f"(v.w)
                 : "memory");
    if (c == 0) atomicAdd(&g_cnt[g], 1.0f);
}

__global__ void head_kernel(const float* __restrict__ wd,
                            const float* __restrict__ bd,
                            float* __restrict__ out)
{
    int g = threadIdx.x;   // 256 threads, one per graph
    float cnt = fmaxf(g_cnt[g], 1.0f);
    float inv = 1.0f / cnt;
    float z0 = __ldg(&bd[0]);
    float z1 = __ldg(&bd[1]);
#pragma unroll
    for (int k = 0; k < 32; k++) {
        float p = g_pool[g * 32 + k] * inv;
        z0 = fmaf(p, __ldg(&wd[k * 2 + 0]), z0);
        z1 = fmaf(p, __ldg(&wd[k * 2 + 1]), z1);
    }
    float m  = fmaxf(z0, z1);
    float e0 = __expf(z0 - m);
    float e1 = __expf(z1 - m);
    float s  = 1.0f / (e0 + e1);
    out[g * 2 + 0] = e0 * s;
    out[g * 2 + 1] = e1 * s;
}

// ---------------------------------------------------------------------------
// Launch
// ---------------------------------------------------------------------------
extern "C" void kernel_launch(void* const* d_in, const int* in_sizes, int n_in,
                              void* d_out, int out_size)
{
    const float* x    = (const float*)d_in[0];
    const float* ew   = (const float*)d_in[1];
    const int*   er   = (const int*)  d_in[2];
    const int*   ec   = (const int*)  d_in[3];
    const int*   seg  = (const int*)  d_in[4];
    const float* w1_1 = (const float*)d_in[5];
    const float* w2_1 = (const float*)d_in[6];
    const float* b_1  = (const float*)d_in[7];
    const float* w1_2 = (const float*)d_in[8];
    const float* w2_2 = (const float*)d_in[9];
    const float* b_2  = (const float*)d_in[10];
    const float* w1_3 = (const float*)d_in[11];
    const float* w2_3 = (const float*)d_in[12];
    const float* b_3  = (const float*)d_in[13];
    const float* wd   = (const float*)d_in[14];
    const float* bd   = (const float*)d_in[15];
    float* out = (float*)d_out;

    const int n = in_sizes[0] / 30;   // 50000
    const int E = in_sizes[1];        // 800000

    float *H, *A1, *A2, *A3;
    cudaGetSymbolAddress((void**)&H,  g_h);
    cudaGetSymbolAddress((void**)&A1, g_a1);
    cudaGetSymbolAddress((void**)&A2, g_a2);
    cudaGetSymbolAddress((void**)&A3, g_a3);

    // dynamic smem sizes: (2*FIN*FOUT + FOUT) * 4 bytes
    const int sm1 = (2 * 30  * 128 + 128) * 4;   // 31232
    const int sm2 = (2 * 128 * 64  + 64)  * 4;   // 65792 (>48KB: opt in)
    const int sm3 = (2 * 64  * 32  + 32)  * 4;   // 16512

    cudaFuncSetAttribute(gemm_dual<128, 64, true>,
                         cudaFuncAttributeMaxDynamicSharedMemorySize, sm2);

    // ---- Layer 1: 30 -> 128 ----
    {
        int rows_per_block = (256 / (128 / 4)) * 4;  // 32
        int blocks = (n + rows_per_block - 1) / rows_per_block;
        gemm_dual<30, 128, false><<<blocks, 256, sm1>>>(x, w1_1, w2_1, b_1, H, A1, n);
        int total = E * (128 / 4);
        scatter_edges<128><<<(total + 255) / 256, 256>>>(H, er, ec, ew, A1, E);
    }
    // ---- Layer 2: 128 -> 64 ----
    {
        int rows_per_block = (256 / (64 / 4)) * 4;   // 64
        int blocks = (n + rows_per_block - 1) / rows_per_block;
        gemm_dual<128, 64, true><<<blocks, 256, sm2>>>(A1, w1_2, w2_2, b_2, H, A2, n);
        int total = E * (64 / 4);
        scatter_edges<64><<<(total + 255) / 256, 256>>>(H, er, ec, ew, A2, E);
    }
    // ---- Layer 3: 64 -> 32 ----
    {
        int rows_per_block = (256 / (32 / 4)) * 4;   // 128
        int blocks = (n + rows_per_block - 1) / rows_per_block;
        gemm_dual<64, 32, true><<<blocks, 256, sm3>>>(A2, w1_3, w2_3, b_3, H, A3, n);
        int total = E * (32 / 4);
        scatter_edges<32><<<(total + 255) / 256, 256>>>(H, er, ec, ew, A3, E);
    }

    // ---- Global avg pool + head ----
    zero_pool_kernel<<<(GG * 32 + 255) / 256, 256>>>();
    pool_kernel<<<(n * 8 + 255) / 256, 256>>>(A3, seg, n);
    head_kernel<<<1, GG>>>(wd, bd, out);
}

// round 2
// speedup vs baseline: 1.2232x; 1.2232x over previous
#include <cuda_runtime.h>
#include <cuda_bf16.h>

// ---------------------------------------------------------------------------
// Net_7335804141892: 3x GCSConv (out = relu(A@(xW1) + xW2 + b)) -> global avg
// pool per graph -> dense(32->2) -> softmax.
// N=50000 nodes, E=800000 edges, G=256 graphs, channels 30->128->64->32.
//
// Round 2: replace atomic edge-scatter with on-device CSR build (per replay)
// + gather-based warp-per-row aggregation (no feature atomics), fuse ReLU
// into aggregation output and fuse the global pool into layer-3 aggregation.
// ---------------------------------------------------------------------------

#define NN 50000
#define EE 800000
#define GG 256
#define SCAN_B 1024
#define SCAN_NB ((NN + SCAN_B - 1) / SCAN_B)   // 49

// Scratch (device globals; no allocation allowed).
__device__ float g_h [NN * 128];   // h = x @ W1 (per layer, reused)
__device__ float g_a1[NN * 128];   // layer1 xW2+b -> in-place layer1 output
__device__ float g_a2[NN * 64];    // layer2 xW2+b -> in-place layer2 output
__device__ float g_a3[NN * 32];    // layer3 xW2+b (consumed by fused pool)
__device__ float g_pool[GG * 32];  // per-graph feature sums
__device__ float g_cnt [GG];       // per-graph node counts

// CSR scratch
__device__ int   g_deg [NN];        // histogram of edge_row
__device__ int   g_rp  [NN + 1];    // row pointers
__device__ int   g_cur [NN];        // fill cursors
__device__ int   g_bsum[SCAN_NB];   // block sums for scan
__device__ int   g_ssrc[EE];        // edge sources, grouped by dest row
__device__ float g_sw  [EE];        // edge weights, grouped by dest row

// ---------------------------------------------------------------------------
// Dual GEMM: H[i,:] = X[i,:] @ W1 ;  A[i,:] = X[i,:] @ W2 + b
// (inputs are post-relu now; aggregation applies relu before storing)
// ---------------------------------------------------------------------------
template <int FIN, int FOUT>
__global__ void __launch_bounds__(256) gemm_dual(
    const float* __restrict__ X,
    const float* __restrict__ W1,
    const float* __restrict__ W2,
    const float* __restrict__ Bv,
    float* __restrict__ H,
    float* __restrict__ A,
    int n)
{
    constexpr int TPR = FOUT / 4;      // threads covering one row (4 cols each)
    constexpr int RG  = 256 / TPR;     // row-groups per block
    constexpr int R   = 4;             // rows per thread

    extern __shared__ float sm[];
    float* sW1 = sm;
    float* sW2 = sm + FIN * FOUT;
    float* sB  = sm + 2 * FIN * FOUT;

    for (int i = threadIdx.x; i < FIN * FOUT; i += 256) {
        sW1[i] = W1[i];
        sW2[i] = W2[i];
    }
    for (int i = threadIdx.x; i < FOUT; i += 256) sB[i] = Bv[i];
    __syncthreads();

    const int c4   = (threadIdx.x % TPR) * 4;
    const int rg   = threadIdx.x / TPR;
    const int row0 = (blockIdx.x * RG + rg) * R;
    if (row0 >= n) return;

    float acc1[R][4];
    float acc2[R][4];
#pragma unroll
    for (int r = 0; r < R; r++)
#pragma unroll
        for (int j = 0; j < 4; j++) { acc1[r][j] = 0.f; acc2[r][j] = 0.f; }

    const bool full = (row0 + R <= n);

    if (full) {
#pragma unroll 4
        for (int k = 0; k < FIN; k++) {
            const float4 w1v = *(const float4*)&sW1[k * FOUT + c4];
            const float4 w2v = *(const float4*)&sW2[k * FOUT + c4];
#pragma unroll
            for (int r = 0; r < R; r++) {
                float xv = __ldg(&X[(size_t)(row0 + r) * FIN + k]);
                acc1[r][0] = fmaf(xv, w1v.x, acc1[r][0]);
                acc1[r][1] = fmaf(xv, w1v.y, acc1[r][1]);
                acc1[r][2] = fmaf(xv, w1v.z, acc1[r][2]);
                acc1[r][3] = fmaf(xv, w1v.w, acc1[r][3]);
                acc2[r][0] = fmaf(xv, w2v.x, acc2[r][0]);
                acc2[r][1] = fmaf(xv, w2v.y, acc2[r][1]);
                acc2[r][2] = fmaf(xv, w2v.z, acc2[r][2]);
                acc2[r][3] = fmaf(xv, w2v.w, acc2[r][3]);
            }
        }
    } else {
        for (int k = 0; k < FIN; k++) {
            const float4 w1v = *(const float4*)&sW1[k * FOUT + c4];
            const float4 w2v = *(const float4*)&sW2[k * FOUT + c4];
#pragma unroll
            for (int r = 0; r < R; r++) {
                int row = row0 + r;
                float xv = (row < n) ? __ldg(&X[(size_t)row * FIN + k]) : 0.f;
                acc1[r][0] = fmaf(xv, w1v.x, acc1[r][0]);
                acc1[r][1] = fmaf(xv, w1v.y, acc1[r][1]);
                acc1[r][2] = fmaf(xv, w1v.z, acc1[r][2]);
                acc1[r][3] = fmaf(xv, w1v.w, acc1[r][3]);
                acc2[r][0] = fmaf(xv, w2v.x, acc2[r][0]);
                acc2[r][1] = fmaf(xv, w2v.y, acc2[r][1]);
                acc2[r][2] = fmaf(xv, w2v.z, acc2[r][2]);
                acc2[r][3] = fmaf(xv, w2v.w, acc2[r][3]);
            }
        }
    }

    const float4 bb = *(const float4*)&sB[c4];
#pragma unroll
    for (int r = 0; r < R; r++) {
        int row = row0 + r;
        if (row < n) {
            float4 o1 = make_float4(acc1[r][0], acc1[r][1], acc1[r][2], acc1[r][3]);
            float4 o2 = make_float4(acc2[r][0] + bb.x, acc2[r][1] + bb.y,
                                    acc2[r][2] + bb.z, acc2[r][3] + bb.w);
            *(float4*)&H[(size_t)row * FOUT + c4] = o1;
            *(float4*)&A[(size_t)row * FOUT + c4] = o2;
        }
    }
}

// ---------------------------------------------------------------------------
// CSR build kernels (run every replay; graph-capturable)
// ---------------------------------------------------------------------------
__global__ void zero_misc_kernel(int n)
{
    int i = blockIdx.x * blockDim.x + threadIdx.x;
    if (i < n)       g_deg[i] = 0;
    if (i < GG * 32) g_pool[i] = 0.f;
    if (i < GG)      g_cnt[i]  = 0.f;
}

__global__ void hist_kernel(const int* __restrict__ er, int E)
{
    int e = blockIdx.x * blockDim.x + threadIdx.x;
    if (e < E) atomicAdd(&g_deg[__ldg(&er[e])], 1);
}

// block-level exclusive scan of g_deg -> g_rp (block-local), block totals -> g_bsum
__global__ void __launch_bounds__(SCAN_B) scan1_kernel(int n)
{
    __shared__ int wsum[32];
    int i = blockIdx.x * SCAN_B + threadIdx.x;
    int v = (i < n) ? g_deg[i] : 0;
    int lane = threadIdx.x & 31, wid = threadIdx.x >> 5;

    int s = v;
#pragma unroll
    for (int o = 1; o < 32; o <<= 1) {
        int t = __shfl_up_sync(0xFFFFFFFFu, s, o);
        if (lane >= o) s += t;
    }
    if (lane == 31) wsum[wid] = s;
    __syncthreads();
    if (wid == 0) {
        int ws = wsum[lane];
#pragma unroll
        for (int o = 1; o < 32; o <<= 1) {
            int t = __shfl_up_sync(0xFFFFFFFFu, ws, o);
            if (lane >= o) ws += t;
        }
        wsum[lane] = ws;
    }
    __syncthreads();
    int excl = s - v + ((wid > 0) ? wsum[wid - 1] : 0);
    if (i < n) g_rp[i] = excl;
    if (threadIdx.x == 0) g_bsum[blockIdx.x] = wsum[31];
}

__global__ void scan2_kernel(int nb, int n, int E)
{
    int acc = 0;
    for (int b = 0; b < nb; b++) { int t = g_bsum[b]; g_bsum[b] = acc; acc += t; }
    g_rp[n] = E;
}

__global__ void __launch_bounds__(SCAN_B) scan3_kernel(int n)
{
    int i = blockIdx.x * SCAN_B + threadIdx.x;
    if (i < n) {
        int v = g_rp[i] + g_bsum[blockIdx.x];
        g_rp[i]  = v;
        g_cur[i] = v;
    }
}

__global__ void fill_kernel(const int* __restrict__ er,
                            const int* __restrict__ ec,
                            const float* __restrict__ ew, int E)
{
    int e = blockIdx.x * blockDim.x + threadIdx.x;
    if (e >= E) return;
    int r   = __ldg(&er[e]);
    int pos = atomicAdd(&g_cur[r], 1);
    g_ssrc[pos] = __ldg(&ec[e]);
    g_sw[pos]   = __ldg(&ew[e]);
}

// ---------------------------------------------------------------------------
// Gather aggregation: one warp per destination row.
//   out[r,:] = relu( sum_{e in row r} w_e * H[src_e,:]  +  A[r,:] )
// EPI = 32/TPR edges processed concurrently per warp-iteration; cross-lane
// shfl reduction combines edge-slot partials. POOL fuses the global avg-pool
// reduction (layer 3) instead of storing the row.
// ---------------------------------------------------------------------------
template <int FOUT, bool POOL>
__global__ void __launch_bounds__(256) agg_rows(
    const float* __restrict__ H,
    float* __restrict__ A,                 // in: xW2+b, out: activated result
    const int* __restrict__ seg,
    int n)
{
    constexpr int TPR = FOUT / 4;          // 32 / 16 / 8
    constexpr int EPI = 32 / TPR;          // 1 / 2 / 4

    int warp = (blockIdx.x * blockDim.x + threadIdx.x) >> 5;
    if (warp >= n) return;
    int lane = threadIdx.x & 31;
    int cl   = lane % TPR;                 // column chunk (4 floats)
    int es   = lane / TPR;                 // edge slot

    int begin = __ldg(&g_rp[warp]);
    int end   = __ldg(&g_rp[warp + 1]);

    float4 acc = make_float4(0.f, 0.f, 0.f, 0.f);
#pragma unroll 2
    for (int i = begin + es; i < end; i += EPI) {
        int   src = __ldg(&g_ssrc[i]);
        float w   = __ldg(&g_sw[i]);
        const float4 h = *(const float4*)&H[(size_t)src * FOUT + cl * 4];
        acc.x = fmaf(w, h.x, acc.x);
        acc.y = fmaf(w, h.y, acc.y);
        acc.z = fmaf(w, h.z, acc.z);
        acc.w = fmaf(w, h.w, acc.w);
    }

    // reduce edge-slot partials (lanes with equal cl)
#pragma unroll
    for (int off = TPR; off < 32; off <<= 1) {
        acc.x += __shfl_xor_sync(0xFFFFFFFFu, acc.x, off);
        acc.y += __shfl_xor_sync(0xFFFFFFFFu, acc.y, off);
        acc.z += __shfl_xor_sync(0xFFFFFFFFu, acc.z, off);
        acc.w += __shfl_xor_sync(0xFFFFFFFFu, acc.w, off);
    }

    if (es == 0) {
        const float4 base = *(const float4*)&A[(size_t)warp * FOUT + cl * 4];
        float4 o;
        o.x = fmaxf(acc.x + base.x, 0.f);
        o.y = fmaxf(acc.y + base.y, 0.f);
        o.z = fmaxf(acc.z + base.z, 0.f);
        o.w = fmaxf(acc.w + base.w, 0.f);
        if (POOL) {
            int g = __ldg(&seg[warp]);
            float* dst = &g_pool[g * 32 + cl * 4];
            asm volatile("red.global.add.v4.f32 [%0], {%1,%2,%3,%4};"
                         :: "l"(dst), "f"(o.x), "f"(o.y), "f"(o.z), "f"(o.w)
                         : "memory");
            if (cl == 0) atomicAdd(&g_cnt[g], 1.0f);
        } else {
            *(float4*)&A[(size_t)warp * FOUT + cl * 4] = o;
        }
    }
}

__global__ void head_kernel(const float* __restrict__ wd,
                            const float* __restrict__ bd,
                            float* __restrict__ out)
{
    int g = threadIdx.x;   // 256 threads, one per graph
    float cnt = fmaxf(g_cnt[g], 1.0f);
    float inv = 1.0f / cnt;
    float z0 = __ldg(&bd[0]);
    float z1 = __ldg(&bd[1]);
#pragma unroll
    for (int k = 0; k < 32; k++) {
        float p = g_pool[g * 32 + k] * inv;
        z0 = fmaf(p, __ldg(&wd[k * 2 + 0]), z0);
        z1 = fmaf(p, __ldg(&wd[k * 2 + 1]), z1);
    }
    float m  = fmaxf(z0, z1);
    float e0 = __expf(z0 - m);
    float e1 = __expf(z1 - m);
    float s  = 1.0f / (e0 + e1);
    out[g * 2 + 0] = e0 * s;
    out[g * 2 + 1] = e1 * s;
}

// ---------------------------------------------------------------------------
// Launch
// ---------------------------------------------------------------------------
extern "C" void kernel_launch(void* const* d_in, const int* in_sizes, int n_in,
                              void* d_out, int out_size)
{
    const float* x    = (const float*)d_in[0];
    const float* ew   = (const float*)d_in[1];
    const int*   er   = (const int*)  d_in[2];
    const int*   ec   = (const int*)  d_in[3];
    const int*   seg  = (const int*)  d_in[4];
    const float* w1_1 = (const float*)d_in[5];
    const float* w2_1 = (const float*)d_in[6];
    const float* b_1  = (const float*)d_in[7];
    const float* w1_2 = (const float*)d_in[8];
    const float* w2_2 = (const float*)d_in[9];
    const float* b_2  = (const float*)d_in[10];
    const float* b2_unused = b_2; (void)b2_unused;
    const float* w1_3 = (const float*)d_in[11];
    const float* w2_3 = (const float*)d_in[12];
    const float* b_3  = (const float*)d_in[13];
    const float* wd   = (const float*)d_in[14];
    const float* bd   = (const float*)d_in[15];
    float* out = (float*)d_out;

    const int n = in_sizes[0] / 30;   // 50000
    const int E = in_sizes[1];        // 800000

    float *H, *A1, *A2, *A3;
    cudaGetSymbolAddress((void**)&H,  g_h);
    cudaGetSymbolAddress((void**)&A1, g_a1);
    cudaGetSymbolAddress((void**)&A2, g_a2);
    cudaGetSymbolAddress((void**)&A3, g_a3);

    // ---- CSR build (every replay; all plain kernels) ----
    zero_misc_kernel<<<(n + 255) / 256, 256>>>(n);
    hist_kernel<<<(E + 255) / 256, 256>>>(er, E);
    scan1_kernel<<<SCAN_NB, SCAN_B>>>(n);
    scan2_kernel<<<1, 1>>>(SCAN_NB, n, E);
    scan3_kernel<<<SCAN_NB, SCAN_B>>>(n);
    fill_kernel<<<(E + 255) / 256, 256>>>(er, ec, ew, E);

    // dynamic smem sizes: (2*FIN*FOUT + FOUT) * 4 bytes
    const int sm1 = (2 * 30  * 128 + 128) * 4;   // 31232
    const int sm2 = (2 * 128 * 64  + 64)  * 4;   // 65792 (>48KB: opt in)
    const int sm3 = (2 * 64  * 32  + 32)  * 4;   // 16512

    cudaFuncSetAttribute(gemm_dual<128, 64>,
                         cudaFuncAttributeMaxDynamicSharedMemorySize, sm2);

    const int agg_blocks = (n * 32 + 255) / 256;

    // ---- Layer 1: 30 -> 128 ----
    {
        int rows_per_block = (256 / (128 / 4)) * 4;  // 32
        int blocks = (n + rows_per_block - 1) / rows_per_block;
        gemm_dual<30, 128><<<blocks, 256, sm1>>>(x, w1_1, w2_1, b_1, H, A1, n);
        agg_rows<128, false><<<agg_blocks, 256>>>(H, A1, seg, n);
    }
    // ---- Layer 2: 128 -> 64 ----
    {
        int rows_per_block = (256 / (64 / 4)) * 4;   // 64
        int blocks = (n + rows_per_block - 1) / rows_per_block;
        gemm_dual<128, 64><<<blocks, 256, sm2>>>(A1, w1_2, w2_2, b_2, H, A2, n);
        agg_rows<64, false><<<agg_blocks, 256>>>(H, A2, seg, n);
    }
    // ---- Layer 3: 64 -> 32 (aggregation fuses relu + global pool) ----
    {
        int rows_per_block = (256 / (32 / 4)) * 4;   // 128
        int blocks = (n + rows_per_block - 1) / rows_per_block;
        gemm_dual<64, 32><<<blocks, 256, sm3>>>(A2, w1_3, w2_3, b_3, H, A3, n);
        agg_rows<32, true><<<agg_blocks, 256>>>(H, A3, seg, n);
    }

    // ---- Head ----
    head_kernel<<<1, GG>>>(wd, bd, out);
}

// round 3
// speedup vs baseline: 1.2778x; 1.0446x over previous
#include <cuda_runtime.h>
#include <cuda_bf16.h>

// ---------------------------------------------------------------------------
// Net_7335804141892: 3x GCSConv (out = relu(A@(xW1) + xW2 + b)) -> global avg
// pool per graph -> dense(32->2) -> softmax.
// N=50000 nodes, E=800000 edges, G=256 graphs, channels 30->128->64->32.
//
// Round 3: f32x2 packed FMA (FFMA2) in the dual GEMMs (2x fma-pipe tput,
// bit-identical rounding), vectorized X loads, 8 rows/thread; warp-parallel
// block-sum scan. CSR gather aggregation unchanged.
// ---------------------------------------------------------------------------

#define NN 50000
#define EE 800000
#define GG 256
#define SCAN_B 1024
#define SCAN_NB ((NN + SCAN_B - 1) / SCAN_B)   // 49

// Scratch (device globals; no allocation allowed).
__device__ float g_h [NN * 128];   // h = x @ W1 (per layer, reused)
__device__ float g_a1[NN * 128];   // layer1 xW2+b -> in-place layer1 output
__device__ float g_a2[NN * 64];    // layer2 xW2+b -> in-place layer2 output
__device__ float g_a3[NN * 32];    // layer3 xW2+b (consumed by fused pool)
__device__ float g_pool[GG * 32];  // per-graph feature sums
__device__ float g_cnt [GG];       // per-graph node counts

// CSR scratch
__device__ int   g_deg [NN];        // histogram of edge_row
__device__ int   g_rp  [NN + 1];    // row pointers
__device__ int   g_cur [NN];        // fill cursors
__device__ int   g_bsum[SCAN_NB];   // block sums for scan
__device__ int   g_ssrc[EE];        // edge sources, grouped by dest row
__device__ float g_sw  [EE];        // edge weights, grouped by dest row

// ---- f32x2 packed helpers -------------------------------------------------
__device__ __forceinline__ unsigned long long pk2(float a, float b) {
    unsigned long long r;
    asm("mov.b64 %0, {%1, %2};" : "=l"(r) : "f"(a), "f"(b));
    return r;
}
__device__ __forceinline__ void fma2(unsigned long long& d,
                                     unsigned long long a,
                                     unsigned long long b) {
    asm("fma.rn.f32x2 %0, %1, %2, %0;" : "+l"(d) : "l"(a), "l"(b));
}
__device__ __forceinline__ void upk2(float& lo, float& hi, unsigned long long v) {
    asm("mov.b64 {%0, %1}, %2;" : "=f"(lo), "=f"(hi) : "l"(v));
}

// ---------------------------------------------------------------------------
// Dual GEMM: H[i,:] = X[i,:] @ W1 ;  A[i,:] = X[i,:] @ W2 + b
// f32x2 packed accumulation: 4 FFMA2 per (k, row) instead of 8 FFMA.
// ---------------------------------------------------------------------------
template <int FIN, int FOUT>
__global__ void __launch_bounds__(256) gemm_dual(
    const float* __restrict__ X,
    const float* __restrict__ W1,
    const float* __restrict__ W2,
    const float* __restrict__ Bv,
    float* __restrict__ H,
    float* __restrict__ A,
    int n)
{
    constexpr int TPR = FOUT / 4;       // threads covering one row (4 cols each)
    constexpr int RG  = 256 / TPR;      // row-groups per block
    constexpr int R   = 8;              // rows per thread
    constexpr int KV  = (FIN % 4 == 0) ? 4 : 2;  // X-vector width

    extern __shared__ float sm[];
    float* sW1 = sm;
    float* sW2 = sm + FIN * FOUT;
    float* sB  = sm + 2 * FIN * FOUT;

    for (int i = threadIdx.x; i < FIN * FOUT; i += 256) {
        sW1[i] = W1[i];
        sW2[i] = W2[i];
    }
    for (int i = threadIdx.x; i < FOUT; i += 256) sB[i] = Bv[i];
    __syncthreads();

    const int c4   = (threadIdx.x % TPR) * 4;
    const int rg   = threadIdx.x / TPR;
    const int row0 = (blockIdx.x * RG + rg) * R;
    if (row0 >= n) return;

    unsigned long long acc1[R][2];
    unsigned long long acc2[R][2];
#pragma unroll
    for (int r = 0; r < R; r++) {
        acc1[r][0] = 0ull; acc1[r][1] = 0ull;
        acc2[r][0] = 0ull; acc2[r][1] = 0ull;
    }

    const bool full = (row0 + R <= n);

    if (full) {
        for (int k0 = 0; k0 < FIN; k0 += KV) {
            // weight pairs for KV consecutive k values
            unsigned long long w1a[KV], w1b[KV], w2a[KV], w2b[KV];
#pragma unroll
            for (int j = 0; j < KV; j++) {
                const ulonglong2 p1 = *(const ulonglong2*)&sW1[(k0 + j) * FOUT + c4];
                const ulonglong2 p2 = *(const ulonglong2*)&sW2[(k0 + j) * FOUT + c4];
                w1a[j] = p1.x; w1b[j] = p1.y;
                w2a[j] = p2.x; w2b[j] = p2.y;
            }
#pragma unroll
            for (int r = 0; r < R; r++) {
                float xv[KV];
                if (KV == 4) {
                    const float4 q = *(const float4*)&X[(size_t)(row0 + r) * FIN + k0];
                    xv[0] = q.x; xv[1] = q.y; xv[2] = q.z; xv[3] = q.w;
                } else {
                    const float2 q = *(const float2*)&X[(size_t)(row0 + r) * FIN + k0];
                    xv[0] = q.x; xv[1] = q.y;
                }
#pragma unroll
                for (int j = 0; j < KV; j++) {
                    const unsigned long long xx = pk2(xv[j], xv[j]);
                    fma2(acc1[r][0], xx, w1a[j]);
                    fma2(acc1[r][1], xx, w1b[j]);
                    fma2(acc2[r][0], xx, w2a[j]);
                    fma2(acc2[r][1], xx, w2b[j]);
                }
            }
        }
    } else {
        for (int k0 = 0; k0 < FIN; k0 += KV) {
            unsigned long long w1a[KV], w1b[KV], w2a[KV], w2b[KV];
#pragma unroll
            for (int j = 0; j < KV; j++) {
                const ulonglong2 p1 = *(const ulonglong2*)&sW1[(k0 + j) * FOUT + c4];
                const ulonglong2 p2 = *(const ulonglong2*)&sW2[(k0 + j) * FOUT + c4];
                w1a[j] = p1.x; w1b[j] = p1.y;
                w2a[j] = p2.x; w2b[j] = p2.y;
            }
#pragma unroll
            for (int r = 0; r < R; r++) {
                if (row0 + r >= n) break;
                float xv[KV];
                if (KV == 4) {
                    const float4 q = *(const float4*)&X[(size_t)(row0 + r) * FIN + k0];
                    xv[0] = q.x; xv[1] = q.y; xv[2] = q.z; xv[3] = q.w;
                } else {
                    const float2 q = *(const float2*)&X[(size_t)(row0 + r) * FIN + k0];
                    xv[0] = q.x; xv[1] = q.y;
                }
#pragma unroll
                for (int j = 0; j < KV; j++) {
                    const unsigned long long xx = pk2(xv[j], xv[j]);
                    fma2(acc1[r][0], xx, w1a[j]);
                    fma2(acc1[r][1], xx, w1b[j]);
                    fma2(acc2[r][0], xx, w2a[j]);
                    fma2(acc2[r][1], xx, w2b[j]);
                }
            }
        }
    }

    const float4 bb = *(const float4*)&sB[c4];
#pragma unroll
    for (int r = 0; r < R; r++) {
        int row = row0 + r;
        if (row < n) {
            float4 o1, o2;
            upk2(o1.x, o1.y, acc1[r][0]);
            upk2(o1.z, o1.w, acc1[r][1]);
            upk2(o2.x, o2.y, acc2[r][0]);
            upk2(o2.z, o2.w, acc2[r][1]);
            o2.x += bb.x; o2.y += bb.y; o2.z += bb.z; o2.w += bb.w;
            *(float4*)&H[(size_t)row * FOUT + c4] = o1;
            *(float4*)&A[(size_t)row * FOUT + c4] = o2;
        }
    }
}

// ---------------------------------------------------------------------------
// CSR build kernels (run every replay; graph-capturable)
// ---------------------------------------------------------------------------
__global__ void zero_misc_kernel(int n)
{
    int i = blockIdx.x * blockDim.x + threadIdx.x;
    if (i < n)       g_deg[i] = 0;
    if (i < GG * 32) g_pool[i] = 0.f;
    if (i < GG)      g_cnt[i]  = 0.f;
}

__global__ void hist_kernel(const int* __restrict__ er, int E)
{
    int e = blockIdx.x * blockDim.x + threadIdx.x;
    if (e < E) atomicAdd(&g_deg[__ldg(&er[e])], 1);
}

// block-level exclusive scan of g_deg -> g_rp (block-local), block totals -> g_bsum
__global__ void __launch_bounds__(SCAN_B) scan1_kernel(int n)
{
    __shared__ int wsum[32];
    int i = blockIdx.x * SCAN_B + threadIdx.x;
    int v = (i < n) ? g_deg[i] : 0;
    int lane = threadIdx.x & 31, wid = threadIdx.x >> 5;

    int s = v;
#pragma unroll
    for (int o = 1; o < 32; o <<= 1) {
        int t = __shfl_up_sync(0xFFFFFFFFu, s, o);
        if (lane >= o) s += t;
    }
    if (lane == 31) wsum[wid] = s;
    __syncthreads();
    if (wid == 0) {
        int ws = wsum[lane];
#pragma unroll
        for (int o = 1; o < 32; o <<= 1) {
            int t = __shfl_up_sync(0xFFFFFFFFu, ws, o);
            if (lane >= o) ws += t;
        }
        wsum[lane] = ws;
    }
    __syncthreads();
    int excl = s - v + ((wid > 0) ? wsum[wid - 1] : 0);
    if (i < n) g_rp[i] = excl;
    if (threadIdx.x == 0) g_bsum[blockIdx.x] = wsum[31];
}

// one-warp scan of the SCAN_NB block sums
__global__ void scan2_kernel(int nb, int n, int E)
{
    int lane = threadIdx.x;
    int carry = 0;
    for (int base = 0; base < nb; base += 32) {
        int i = base + lane;
        int v = (i < nb) ? g_bsum[i] : 0;
        int s = v;
#pragma unroll
        for (int o = 1; o < 32; o <<= 1) {
            int t = __shfl_up_sync(0xFFFFFFFFu, s, o);
            if (lane >= o) s += t;
        }
        if (i < nb) g_bsum[i] = s - v + carry;
        carry += __shfl_sync(0xFFFFFFFFu, s, 31);
    }
    if (lane == 0) g_rp[n] = E;
}

__global__ void __launch_bounds__(SCAN_B) scan3_kernel(int n)
{
    int i = blockIdx.x * SCAN_B + threadIdx.x;
    if (i < n) {
        int v = g_rp[i] + g_bsum[blockIdx.x];
        g_rp[i]  = v;
        g_cur[i] = v;
    }
}

__global__ void fill_kernel(const int* __restrict__ er,
                            const int* __restrict__ ec,
                            const float* __restrict__ ew, int E)
{
    int e = blockIdx.x * blockDim.x + threadIdx.x;
    if (e >= E) return;
    int r   = __ldg(&er[e]);
    int pos = atomicAdd(&g_cur[r], 1);
    g_ssrc[pos] = __ldg(&ec[e]);
    g_sw[pos]   = __ldg(&ew[e]);
}

// ---------------------------------------------------------------------------
// Gather aggregation: one warp per destination row.
//   out[r,:] = relu( sum_{e in row r} w_e * H[src_e,:]  +  A[r,:] )
// ---------------------------------------------------------------------------
template <int FOUT, bool POOL>
__global__ void __launch_bounds__(256) agg_rows(
    const float* __restrict__ H,
    float* __restrict__ A,                 // in: xW2+b, out: activated result
    const int* __restrict__ seg,
    int n)
{
    constexpr int TPR = FOUT / 4;          // 32 / 16 / 8
    constexpr int EPI = 32 / TPR;          // 1 / 2 / 4

    int warp = (blockIdx.x * blockDim.x + threadIdx.x) >> 5;
    if (warp >= n) return;
    int lane = threadIdx.x & 31;
    int cl   = lane % TPR;                 // column chunk (4 floats)
    int es   = lane / TPR;                 // edge slot

    int begin = __ldg(&g_rp[warp]);
    int end   = __ldg(&g_rp[warp + 1]);

    float4 acc = make_float4(0.f, 0.f, 0.f, 0.f);
#pragma unroll 2
    for (int i = begin + es; i < end; i += EPI) {
        int   src = __ldg(&g_ssrc[i]);
        float w   = __ldg(&g_sw[i]);
        const float4 h = *(const float4*)&H[(size_t)src * FOUT + cl * 4];
        acc.x = fmaf(w, h.x, acc.x);
        acc.y = fmaf(w, h.y, acc.y);
        acc.z = fmaf(w, h.z, acc.z);
        acc.w = fmaf(w, h.w, acc.w);
    }

#pragma unroll
    for (int off = TPR; off < 32; off <<= 1) {
        acc.x += __shfl_xor_sync(0xFFFFFFFFu, acc.x, off);
        acc.y += __shfl_xor_sync(0xFFFFFFFFu, acc.y, off);
        acc.z += __shfl_xor_sync(0xFFFFFFFFu, acc.z, off);
        acc.w += __shfl_xor_sync(0xFFFFFFFFu, acc.w, off);
    }

    if (es == 0) {
        const float4 base = *(const float4*)&A[(size_t)warp * FOUT + cl * 4];
        float4 o;
        o.x = fmaxf(acc.x + base.x, 0.f);
        o.y = fmaxf(acc.y + base.y, 0.f);
        o.z = fmaxf(acc.z + base.z, 0.f);
        o.w = fmaxf(acc.w + base.w, 0.f);
        if (POOL) {
            int g = __ldg(&seg[warp]);
            float* dst = &g_pool[g * 32 + cl * 4];
            asm volatile("red.global.add.v4.f32 [%0], {%1,%2,%3,%4};"
                         :: "l"(dst), "f"(o.x), "f"(o.y), "f"(o.z), "f"(o.w)
                         : "memory");
            if (cl == 0) atomicAdd(&g_cnt[g], 1.0f);
        } else {
            *(float4*)&A[(size_t)warp * FOUT + cl * 4] = o;
        }
    }
}

__global__ void head_kernel(const float* __restrict__ wd,
                            const float* __restrict__ bd,
                            float* __restrict__ out)
{
    int g = threadIdx.x;   // 256 threads, one per graph
    float cnt = fmaxf(g_cnt[g], 1.0f);
    float inv = 1.0f / cnt;
    float z0 = __ldg(&bd[0]);
    float z1 = __ldg(&bd[1]);
#pragma unroll
    for (int k = 0; k < 32; k++) {
        float p = g_pool[g * 32 + k] * inv;
        z0 = fmaf(p, __ldg(&wd[k * 2 + 0]), z0);
        z1 = fmaf(p, __ldg(&wd[k * 2 + 1]), z1);
    }
    float m  = fmaxf(z0, z1);
    float e0 = __expf(z0 - m);
    float e1 = __expf(z1 - m);
    float s  = 1.0f / (e0 + e1);
    out[g * 2 + 0] = e0 * s;
    out[g * 2 + 1] = e1 * s;
}

// ---------------------------------------------------------------------------
// Launch
// ---------------------------------------------------------------------------
extern "C" void kernel_launch(void* const* d_in, const int* in_sizes, int n_in,
                              void* d_out, int out_size)
{
    const float* x    = (const float*)d_in[0];
    const float* ew   = (const float*)d_in[1];
    const int*   er   = (const int*)  d_in[2];
    const int*   ec   = (const int*)  d_in[3];
    const int*   seg  = (const int*)  d_in[4];
    const float* w1_1 = (const float*)d_in[5];
    const float* w2_1 = (const float*)d_in[6];
    const float* b_1  = (const float*)d_in[7];
    const float* w1_2 = (const float*)d_in[8];
    const float* w2_2 = (const float*)d_in[9];
    const float* b_2  = (const float*)d_in[10];
    const float* w1_3 = (const float*)d_in[11];
    const float* w2_3 = (const float*)d_in[12];
    const float* b_3  = (const float*)d_in[13];
    const float* wd   = (const float*)d_in[14];
    const float* bd   = (const float*)d_in[15];
    float* out = (float*)d_out;

    const int n = in_sizes[0] / 30;   // 50000
    const int E = in_sizes[1];        // 800000

    float *H, *A1, *A2, *A3;
    cudaGetSymbolAddress((void**)&H,  g_h);
    cudaGetSymbolAddress((void**)&A1, g_a1);
    cudaGetSymbolAddress((void**)&A2, g_a2);
    cudaGetSymbolAddress((void**)&A3, g_a3);

    // ---- CSR build (every replay; all plain kernels) ----
    zero_misc_kernel<<<(n + 255) / 256, 256>>>(n);
    hist_kernel<<<(E + 255) / 256, 256>>>(er, E);
    scan1_kernel<<<SCAN_NB, SCAN_B>>>(n);
    scan2_kernel<<<1, 32>>>(SCAN_NB, n, E);
    scan3_kernel<<<SCAN_NB, SCAN_B>>>(n);
    fill_kernel<<<(E + 255) / 256, 256>>>(er, ec, ew, E);

    // dynamic smem sizes: (2*FIN*FOUT + FOUT) * 4 bytes
    const int sm1 = (2 * 30  * 128 + 128) * 4;   // 31232
    const int sm2 = (2 * 128 * 64  + 64)  * 4;   // 65792 (>48KB: opt in)
    const int sm3 = (2 * 64  * 32  + 32)  * 4;   // 16512

    cudaFuncSetAttribute(gemm_dual<128, 64>,
                         cudaFuncAttributeMaxDynamicSharedMemorySize, sm2);

    const int agg_blocks = (n * 32 + 255) / 256;

    // ---- Layer 1: 30 -> 128 ----
    {
        int rows_per_block = (256 / (128 / 4)) * 8;  // 64
        int blocks = (n + rows_per_block - 1) / rows_per_block;
        gemm_dual<30, 128><<<blocks, 256, sm1>>>(x, w1_1, w2_1, b_1, H, A1, n);
        agg_rows<128, false><<<agg_blocks, 256>>>(H, A1, seg, n);
    }
    // ---- Layer 2: 128 -> 64 ----
    {
        int rows_per_block = (256 / (64 / 4)) * 8;   // 128
        int blocks = (n + rows_per_block - 1) / rows_per_block;
        gemm_dual<128, 64><<<blocks, 256, sm2>>>(A1, w1_2, w2_2, b_2, H, A2, n);
        agg_rows<64, false><<<agg_blocks, 256>>>(H, A2, seg, n);
    }
    // ---- Layer 3: 64 -> 32 (aggregation fuses relu + global pool) ----
    {
        int rows_per_block = (256 / (32 / 4)) * 8;   // 256
        int blocks = (n + rows_per_block - 1) / rows_per_block;
        gemm_dual<64, 32><<<blocks, 256, sm3>>>(A2, w1_3, w2_3, b_3, H, A3, n);
        agg_rows<32, true><<<agg_blocks, 256>>>(H, A3, seg, n);
    }

    // ---- Head ----
    head_kernel<<<1, GG>>>(wd, bd, out);
}